// round 2
// baseline (speedup 1.0000x reference)
#include <cuda_runtime.h>
#include <math.h>

#define BATCH  4
#define SEQ    2048
#define DMODEL 1024
#define NHEAD  16
#define HDIM   64
#define NBH    (BATCH * NHEAD)        // 64
#define NTOK   (BATCH * SEQ)          // 8192
#define PROJ_ELEMS ((size_t)NTOK * DMODEL)  // 8388608

// Scratch: qh, kh, vh (each [B,H,S,DK]), ctx [B,S,H*DK], fc [B,S,D]
__device__ float g_scratch[5 * (size_t)NTOK * DMODEL];

enum { EPI_PROJ = 0, EPI_PLAIN = 1, EPI_SCORES = 2, EPI_CTX = 3 };

// Generic 128xBN x K fp32 GEMM, 256 threads, TM=8 x TN=BN/16 per thread.
// A: row-major [M,K] (lda). B: row-major [K,N] (ldb) unless BTRANS, in which
// case B is row-major [N,K] (ldb) and we compute A * B^T.
template <int BN, bool BTRANS, int EPI>
__global__ __launch_bounds__(256) void gemm_kernel(
    const float* __restrict__ A, const float* __restrict__ B,
    const float* __restrict__ bias, float* __restrict__ C,
    int M, int N, int K, int lda, int ldb)
{
    constexpr int BM = 128, BK = 16;
    constexpr int TM = 8, TN = BN / 16;

    __shared__ float As[BK][BM];
    __shared__ float Bs[BK][BN];

    const int tid = threadIdx.x;
    const int tx = tid & 15;
    const int ty = tid >> 4;
    const int m0 = blockIdx.y * BM;
    const int n0 = blockIdx.x * BN;
    const int batch = blockIdx.z;

    if (EPI == EPI_SCORES) {
        A += (size_t)batch * (SEQ * HDIM);
        B += (size_t)batch * (SEQ * HDIM);
    } else if (EPI == EPI_CTX) {
        A += (size_t)batch * ((size_t)SEQ * SEQ);
        B += (size_t)batch * (SEQ * HDIM);
    }

    float acc[TM][TN];
#pragma unroll
    for (int i = 0; i < TM; i++)
#pragma unroll
        for (int j = 0; j < TN; j++) acc[i][j] = 0.f;

    for (int k0 = 0; k0 < K; k0 += BK) {
        // Load A tile -> As[k][m] (transposed for broadcast-friendly reads)
        for (int i = tid; i < BM * (BK / 4); i += 256) {
            int m  = i >> 2;
            int kk = (i & 3) << 2;
            float4 a = *(const float4*)(A + (size_t)(m0 + m) * lda + (k0 + kk));
            As[kk + 0][m] = a.x;
            As[kk + 1][m] = a.y;
            As[kk + 2][m] = a.z;
            As[kk + 3][m] = a.w;
        }
        // Load B tile -> Bs[k][n]
        if (!BTRANS) {
            for (int i = tid; i < BK * (BN / 4); i += 256) {
                int kk = i / (BN / 4);
                int n4 = (i % (BN / 4)) * 4;
                *(float4*)&Bs[kk][n4] =
                    *(const float4*)(B + (size_t)(k0 + kk) * ldb + (n0 + n4));
            }
        } else {
            for (int i = tid; i < BN * (BK / 4); i += 256) {
                int n  = i >> 2;
                int kk = (i & 3) << 2;
                float4 b = *(const float4*)(B + (size_t)(n0 + n) * ldb + (k0 + kk));
                Bs[kk + 0][n] = b.x;
                Bs[kk + 1][n] = b.y;
                Bs[kk + 2][n] = b.z;
                Bs[kk + 3][n] = b.w;
            }
        }
        __syncthreads();

#pragma unroll
        for (int kk = 0; kk < BK; kk++) {
            float ra[TM], rb[TN];
#pragma unroll
            for (int i = 0; i < TM; i++) ra[i] = As[kk][ty * TM + i];
#pragma unroll
            for (int j = 0; j < TN; j++) rb[j] = Bs[kk][tx * TN + j];
#pragma unroll
            for (int i = 0; i < TM; i++)
#pragma unroll
                for (int j = 0; j < TN; j++) acc[i][j] += ra[i] * rb[j];
        }
        __syncthreads();
    }

    // Epilogue
#pragma unroll
    for (int i = 0; i < TM; i++) {
#pragma unroll
        for (int j = 0; j < TN; j++) {
            int row = m0 + ty * TM + i;
            int col = n0 + tx * TN + j;
            float val = acc[i][j];
            if (EPI == EPI_PROJ) {
                // row = b*S + s (token), col = h*DK + d  ->  [b,h,s,d]
                val += bias[col];
                int b = row >> 11;          // / SEQ
                int s = row & (SEQ - 1);
                int h = col >> 6;           // / HDIM
                int d = col & (HDIM - 1);
                C[((((size_t)b * NHEAD + h) * SEQ + s) << 6) + d] = val;
            } else if (EPI == EPI_PLAIN) {
                C[(size_t)row * N + col] = val + bias[col];
            } else if (EPI == EPI_SCORES) {
                C[(size_t)batch * SEQ * SEQ + (size_t)row * SEQ + col] =
                    val * 0.125f;  // DK^-0.5
            } else {  // EPI_CTX: [b, s, h*DK + d]
                int b = batch >> 4;         // / NHEAD
                int h = batch & (NHEAD - 1);
                C[((size_t)b * SEQ + row) * DMODEL + h * HDIM + col] = val;
            }
        }
    }
}

__device__ __forceinline__ float warpMax(float v) {
#pragma unroll
    for (int o = 16; o > 0; o >>= 1) v = fmaxf(v, __shfl_xor_sync(0xffffffffu, v, o));
    return v;
}
__device__ __forceinline__ float warpSum(float v) {
#pragma unroll
    for (int o = 16; o > 0; o >>= 1) v += __shfl_xor_sync(0xffffffffu, v, o);
    return v;
}

// One block (256 threads) per attention row of 2048 floats; softmax in place.
__global__ __launch_bounds__(256) void softmax_kernel(float* __restrict__ attn)
{
    float* p = attn + (size_t)blockIdx.x * SEQ;
    const int tid = threadIdx.x;
    const int lane = tid & 31, wid = tid >> 5;
    __shared__ float sh[8];

    float4 a = *(float4*)(p + tid * 4);
    float4 b = *(float4*)(p + 1024 + tid * 4);

    float m = fmaxf(fmaxf(fmaxf(a.x, a.y), fmaxf(a.z, a.w)),
                    fmaxf(fmaxf(b.x, b.y), fmaxf(b.z, b.w)));
    m = warpMax(m);
    if (!lane) sh[wid] = m;
    __syncthreads();
    if (tid < 32) {
        float t = (tid < 8) ? sh[tid] : -3.4e38f;
        t = warpMax(t);
        if (!tid) sh[0] = t;
    }
    __syncthreads();
    m = sh[0];
    __syncthreads();

    a.x = __expf(a.x - m); a.y = __expf(a.y - m);
    a.z = __expf(a.z - m); a.w = __expf(a.w - m);
    b.x = __expf(b.x - m); b.y = __expf(b.y - m);
    b.z = __expf(b.z - m); b.w = __expf(b.w - m);

    float s = (a.x + a.y + a.z + a.w) + (b.x + b.y + b.z + b.w);
    s = warpSum(s);
    if (!lane) sh[wid] = s;
    __syncthreads();
    if (tid < 32) {
        float t = (tid < 8) ? sh[tid] : 0.f;
        t = warpSum(t);
        if (!tid) sh[0] = t;
    }
    __syncthreads();
    float inv = 1.f / sh[0];

    a.x *= inv; a.y *= inv; a.z *= inv; a.w *= inv;
    b.x *= inv; b.y *= inv; b.z *= inv; b.w *= inv;
    *(float4*)(p + tid * 4) = a;
    *(float4*)(p + 1024 + tid * 4) = b;
}

// One block per token row: x = q + fc; LayerNorm(x) -> out
__global__ __launch_bounds__(256) void ln_kernel(
    const float* __restrict__ q, const float* __restrict__ fc,
    const float* __restrict__ gamma, const float* __restrict__ beta,
    float* __restrict__ out)
{
    const size_t base = (size_t)blockIdx.x * DMODEL;
    const int tid = threadIdx.x;
    const int lane = tid & 31, wid = tid >> 5;
    __shared__ float shs[8];
    __shared__ float shq[8];

    float4 xq = *(const float4*)(q + base + tid * 4);
    float4 xf = *(const float4*)(fc + base + tid * 4);
    float x0 = xq.x + xf.x, x1 = xq.y + xf.y, x2 = xq.z + xf.z, x3 = xq.w + xf.w;

    float s  = x0 + x1 + x2 + x3;
    float sq = x0 * x0 + x1 * x1 + x2 * x2 + x3 * x3;
    s = warpSum(s);
    sq = warpSum(sq);
    if (!lane) { shs[wid] = s; shq[wid] = sq; }
    __syncthreads();
    if (tid < 32) {
        float ts = (tid < 8) ? shs[tid] : 0.f;
        float tq = (tid < 8) ? shq[tid] : 0.f;
        ts = warpSum(ts);
        tq = warpSum(tq);
        if (!tid) { shs[0] = ts; shq[0] = tq; }
    }
    __syncthreads();

    const float inv_n = 1.f / DMODEL;
    float mu  = shs[0] * inv_n;
    float var = shq[0] * inv_n - mu * mu;
    float r = rsqrtf(var + 1e-6f);

    float4 g  = *(const float4*)(gamma + tid * 4);
    float4 be = *(const float4*)(beta + tid * 4);
    float4 y;
    y.x = (x0 - mu) * r * g.x + be.x;
    y.y = (x1 - mu) * r * g.y + be.y;
    y.z = (x2 - mu) * r * g.z + be.z;
    y.w = (x3 - mu) * r * g.w + be.w;
    *(float4*)(out + base + tid * 4) = y;
}

extern "C" void kernel_launch(void* const* d_in, const int* in_sizes, int n_in,
                              void* d_out, int out_size)
{
    const float* q     = (const float*)d_in[0];
    const float* k     = (const float*)d_in[1];
    const float* v     = (const float*)d_in[2];
    const float* Wq    = (const float*)d_in[3];
    const float* bq    = (const float*)d_in[4];
    const float* Wfc   = (const float*)d_in[5];
    const float* bfc   = (const float*)d_in[6];
    const float* gamma = (const float*)d_in[7];
    const float* beta  = (const float*)d_in[8];

    float* out      = (float*)d_out;
    float* x_out    = out;                          // [B,S,D]
    float* attn_out = out + PROJ_ELEMS;             // [B,H,S,S]

    float* base = nullptr;
    cudaGetSymbolAddress((void**)&base, g_scratch);
    float* qh  = base;
    float* kh  = base + PROJ_ELEMS;
    float* vh  = base + 2 * PROJ_ELEMS;
    float* ctx = base + 3 * PROJ_ELEMS;
    float* fcb = base + 4 * PROJ_ELEMS;

    dim3 blk(256);

    // Projections: [8192,1024] @ [1024,1024] + bias -> [B,H,S,DK]
    dim3 gproj(DMODEL / 128, NTOK / 128, 1);
    gemm_kernel<128, false, EPI_PROJ><<<gproj, blk>>>(
        q, Wq, bq, qh, NTOK, DMODEL, DMODEL, DMODEL, DMODEL);
    gemm_kernel<128, false, EPI_PROJ><<<gproj, blk>>>(
        k, Wq, bq, kh, NTOK, DMODEL, DMODEL, DMODEL, DMODEL);
    gemm_kernel<128, false, EPI_PROJ><<<gproj, blk>>>(
        v, Wq, bq, vh, NTOK, DMODEL, DMODEL, DMODEL, DMODEL);

    // Scores: per (b,h): [2048,64] @ [2048,64]^T * scale -> attn region of d_out
    dim3 gsc(SEQ / 128, SEQ / 128, NBH);
    gemm_kernel<128, true, EPI_SCORES><<<gsc, blk>>>(
        qh, kh, nullptr, attn_out, SEQ, SEQ, HDIM, HDIM, HDIM);

    // Softmax rows in place (scores are re-written every replay -> deterministic)
    softmax_kernel<<<NBH * SEQ, blk>>>(attn_out);

    // ctx: per (b,h): attn [2048,2048] @ vh [2048,64] -> [B,S,H*DK]
    dim3 gctx(1, SEQ / 128, NBH);
    gemm_kernel<64, false, EPI_CTX><<<gctx, blk>>>(
        attn_out, vh, nullptr, ctx, SEQ, HDIM, SEQ, SEQ, HDIM);

    // Out projection: [8192,1024] @ [1024,1024] + bias -> fcb
    dim3 gfc(DMODEL / 128, NTOK / 128, 1);
    gemm_kernel<128, false, EPI_PLAIN><<<gfc, blk>>>(
        ctx, Wfc, bfc, fcb, NTOK, DMODEL, DMODEL, DMODEL, DMODEL);

    // Residual + LayerNorm -> x region of d_out
    ln_kernel<<<NTOK, blk>>>(q, fcb, gamma, beta, x_out);
}

// round 6
// speedup vs baseline: 2.9727x; 2.9727x over previous
#include <cuda_runtime.h>
#include <stdint.h>
#include <math.h>

#define BATCH  4
#define SEQ    2048
#define DMODEL 1024
#define NHEAD  16
#define HDIM   64
#define NBH    (BATCH * NHEAD)        // 64
#define NTOK   (BATCH * SEQ)          // 8192
#define PROJ_ELEMS ((size_t)NTOK * DMODEL)  // 8388608

// qh, kh, vhT, ctx, fcb (each PROJ_ELEMS) + WqT + WfcT (1M each)
__device__ float g_scratch[5 * PROJ_ELEMS + 2 * 1024 * 1024];

// ===================== helpers ==============================================
__device__ __forceinline__ uint32_t smem_u32(const void* p) {
    uint32_t a;
    asm("{ .reg .u64 t; cvta.to.shared.u64 t, %1; cvt.u32.u64 %0, t; }"
        : "=r"(a) : "l"(p));
    return a;
}
__device__ __forceinline__ void cp16(void* s, const void* g) {
    asm volatile("cp.async.cg.shared.global [%0], [%1], 16;"
                 :: "r"(smem_u32(s)), "l"(g));
}
__device__ __forceinline__ void cp_commit() {
    asm volatile("cp.async.commit_group;");
}
template <int N>
__device__ __forceinline__ void cp_wait() {
    asm volatile("cp.async.wait_group %0;" :: "n"(N));
}
__device__ __forceinline__ uint32_t f2tf(float x) {
    uint32_t r;
    asm("cvt.rn.tf32.f32 %0, %1;" : "=r"(r) : "f"(x));
    return r;
}
__device__ __forceinline__ void mma_tf32(float* d, const uint32_t* a,
                                         const uint32_t* b) {
    asm volatile(
        "mma.sync.aligned.m16n8k8.row.col.f32.tf32.tf32.f32 "
        "{%0,%1,%2,%3}, {%4,%5,%6,%7}, {%8,%9}, {%0,%1,%2,%3};"
        : "+f"(d[0]), "+f"(d[1]), "+f"(d[2]), "+f"(d[3])
        : "r"(a[0]), "r"(a[1]), "r"(a[2]), "r"(a[3]), "r"(b[0]), "r"(b[1]));
}

// ===================== tf32 mma.sync GEMM ===================================
// D[m][n] = sum_k A[m][k] * B[n][k]   (A:[M,K] lda, B:[N,K] ldb, both K-major)
enum { EPI_PROJ = 0, EPI_PROJV = 1, EPI_SCORES = 2, EPI_CTX = 3, EPI_PLAIN = 4 };

template <int BN, int EPI>
__global__ __launch_bounds__(256, 2) void tc_gemm(
    const float* __restrict__ A, const float* __restrict__ B,
    const float* __restrict__ bias, float* __restrict__ C,
    int K, int lda, int ldb)
{
    constexpr int BM = 128, BK = 16;
    constexpr int LDS_ = BK + 4;                 // 20 floats (80B, 16B-aligned)
    constexpr int WARPS_M = (BN == 128) ? 2 : 4;
    constexpr int WARPS_N = 8 / WARPS_M;
    constexpr int WM = BM / WARPS_M;             // 64 | 32
    constexpr int WN = BN / WARPS_N;             // 32 | 32
    constexpr int MT = WM / 16;                  // 4 | 2
    constexpr int NT = WN / 8;                   // 4

    __shared__ float As[2][BM * LDS_];
    __shared__ float Bs[2][BN * LDS_];

    const int tid  = threadIdx.x;
    const int warp = tid >> 5;
    const int lane = tid & 31;
    const int g    = lane >> 2;      // 0..7
    const int tig  = lane & 3;       // 0..3
    const int warp_m = warp / WARPS_N;
    const int warp_n = warp % WARPS_N;
    const int m0 = blockIdx.y * BM;
    const int n0 = blockIdx.x * BN;
    const int z  = blockIdx.z;

    const float* Ag = A;
    const float* Bg = B;
    if (EPI == EPI_SCORES) { Ag += (size_t)z * SEQ * HDIM; Bg += (size_t)z * SEQ * HDIM; }
    if (EPI == EPI_CTX)    { Ag += (size_t)z * SEQ * SEQ;  Bg += (size_t)z * HDIM * SEQ; }

    const int lr  = tid >> 2;        // 0..63 loader row
    const int lc4 = tid & 3;         // float4 index within BK=16

    float acc[MT][NT][4];
#pragma unroll
    for (int i = 0; i < MT; i++)
#pragma unroll
        for (int j = 0; j < NT; j++)
#pragma unroll
            for (int r = 0; r < 4; r++) acc[i][j][r] = 0.f;

    const int nit = K / BK;

    auto load_stage = [&](int s, int k0) {
        // A: 128 rows x 16 k  (512 float4, 2 per thread)
        cp16(&As[s][lr * LDS_ + lc4 * 4],
             Ag + (size_t)(m0 + lr) * lda + k0 + lc4 * 4);
        cp16(&As[s][(lr + 64) * LDS_ + lc4 * 4],
             Ag + (size_t)(m0 + lr + 64) * lda + k0 + lc4 * 4);
        // B: BN rows x 16 k
        cp16(&Bs[s][lr * LDS_ + lc4 * 4],
             Bg + (size_t)(n0 + lr) * ldb + k0 + lc4 * 4);
        if (BN == 128)
            cp16(&Bs[s][(lr + 64) * LDS_ + lc4 * 4],
                 Bg + (size_t)(n0 + lr + 64) * ldb + k0 + lc4 * 4);
        cp_commit();
    };

    load_stage(0, 0);

    for (int it = 0; it < nit; it++) {
        if (it + 1 < nit) {
            load_stage((it + 1) & 1, (it + 1) * BK);
            cp_wait<1>();
        } else {
            cp_wait<0>();
        }
        __syncthreads();

        const float* as = As[it & 1];
        const float* bs = Bs[it & 1];
#pragma unroll
        for (int kt = 0; kt < BK / 8; kt++) {
            uint32_t af[MT][4];
#pragma unroll
            for (int i = 0; i < MT; i++) {
                int r = warp_m * WM + i * 16;
                const float* p = as + (r + g) * LDS_ + kt * 8 + tig;
                af[i][0] = f2tf(p[0]);
                af[i][1] = f2tf(p[8 * LDS_]);
                af[i][2] = f2tf(p[4]);
                af[i][3] = f2tf(p[8 * LDS_ + 4]);
            }
            uint32_t bf[NT][2];
#pragma unroll
            for (int j = 0; j < NT; j++) {
                int n = warp_n * WN + j * 8;
                const float* p = bs + (n + g) * LDS_ + kt * 8 + tig;
                bf[j][0] = f2tf(p[0]);
                bf[j][1] = f2tf(p[4]);
            }
#pragma unroll
            for (int i = 0; i < MT; i++)
#pragma unroll
                for (int j = 0; j < NT; j++)
                    mma_tf32(acc[i][j], af[i], bf[j]);
        }
        __syncthreads();
    }

    // ---------------- epilogue ----------------------------------------------
#pragma unroll
    for (int i = 0; i < MT; i++) {
        int r0 = m0 + warp_m * WM + i * 16 + g;
        int r1 = r0 + 8;
#pragma unroll
        for (int j = 0; j < NT; j++) {
            int c = n0 + warp_n * WN + j * 8 + tig * 2;
            float d0 = acc[i][j][0], d1 = acc[i][j][1];
            float d2 = acc[i][j][2], d3 = acc[i][j][3];

            if (EPI == EPI_SCORES) {
                float* base = C + (size_t)z * SEQ * SEQ + c;
                *(float2*)(base + (size_t)r0 * SEQ) =
                    make_float2(d0 * 0.125f, d1 * 0.125f);
                *(float2*)(base + (size_t)r1 * SEQ) =
                    make_float2(d2 * 0.125f, d3 * 0.125f);
            } else if (EPI == EPI_PLAIN) {
                float2 bb = *(const float2*)(bias + c);
                *(float2*)(C + (size_t)r0 * DMODEL + c) =
                    make_float2(d0 + bb.x, d1 + bb.y);
                *(float2*)(C + (size_t)r1 * DMODEL + c) =
                    make_float2(d2 + bb.x, d3 + bb.y);
            } else if (EPI == EPI_PROJ) {
                float2 bb = *(const float2*)(bias + c);
                int h = c >> 6, dd = c & 63;
                {
                    int b = r0 >> 11, s = r0 & (SEQ - 1);
                    *(float2*)(C + ((((size_t)b * NHEAD + h) * SEQ + s) << 6) + dd) =
                        make_float2(d0 + bb.x, d1 + bb.y);
                }
                {
                    int b = r1 >> 11, s = r1 & (SEQ - 1);
                    *(float2*)(C + ((((size_t)b * NHEAD + h) * SEQ + s) << 6) + dd) =
                        make_float2(d2 + bb.x, d3 + bb.y);
                }
            } else if (EPI == EPI_PROJV) {
                // vhT[b][h][d][s] = val
                float2 bb = *(const float2*)(bias + c);
                int h = c >> 6, dd = c & 63;
                {
                    int b = r0 >> 11, s = r0 & (SEQ - 1);
                    float* base = C + (((size_t)b * NHEAD + h) * HDIM + dd) * SEQ + s;
                    base[0]   = d0 + bb.x;
                    base[SEQ] = d1 + bb.y;
                }
                {
                    int b = r1 >> 11, s = r1 & (SEQ - 1);
                    float* base = C + (((size_t)b * NHEAD + h) * HDIM + dd) * SEQ + s;
                    base[0]   = d2 + bb.x;
                    base[SEQ] = d3 + bb.y;
                }
            } else {  // EPI_CTX: C[b][s][h*64 + c]
                int b = z >> 4, h = z & (NHEAD - 1);
                *(float2*)(C + ((size_t)b * SEQ + r0) * DMODEL + h * HDIM + c) =
                    make_float2(d0, d1);
                *(float2*)(C + ((size_t)b * SEQ + r1) * DMODEL + h * HDIM + c) =
                    make_float2(d2, d3);
            }
        }
    }
}

// ===================== transpose (Wq, Wfc) ==================================
__global__ __launch_bounds__(256) void transpose_kernel(
    const float* __restrict__ in, float* __restrict__ out)
{
    __shared__ float tile[32][33];
    int x0 = blockIdx.x * 32, y0 = blockIdx.y * 32;
    for (int i = threadIdx.y; i < 32; i += 8)
        tile[i][threadIdx.x] = in[(size_t)(y0 + i) * DMODEL + x0 + threadIdx.x];
    __syncthreads();
    for (int i = threadIdx.y; i < 32; i += 8)
        out[(size_t)(x0 + i) * DMODEL + y0 + threadIdx.x] = tile[threadIdx.x][i];
}

// ===================== softmax / layernorm ==================================
__device__ __forceinline__ float warpMax(float v) {
#pragma unroll
    for (int o = 16; o > 0; o >>= 1) v = fmaxf(v, __shfl_xor_sync(0xffffffffu, v, o));
    return v;
}
__device__ __forceinline__ float warpSum(float v) {
#pragma unroll
    for (int o = 16; o > 0; o >>= 1) v += __shfl_xor_sync(0xffffffffu, v, o);
    return v;
}

__global__ __launch_bounds__(256) void softmax_kernel(float* __restrict__ attn)
{
    float* p = attn + (size_t)blockIdx.x * SEQ;
    const int tid = threadIdx.x;
    const int lane = tid & 31, wid = tid >> 5;
    __shared__ float sh[8];

    float4 a = *(float4*)(p + tid * 4);
    float4 b = *(float4*)(p + 1024 + tid * 4);

    float m = fmaxf(fmaxf(fmaxf(a.x, a.y), fmaxf(a.z, a.w)),
                    fmaxf(fmaxf(b.x, b.y), fmaxf(b.z, b.w)));
    m = warpMax(m);
    if (!lane) sh[wid] = m;
    __syncthreads();
    if (tid < 32) {
        float t = (tid < 8) ? sh[tid] : -3.4e38f;
        t = warpMax(t);
        if (!tid) sh[0] = t;
    }
    __syncthreads();
    m = sh[0];
    __syncthreads();

    a.x = __expf(a.x - m); a.y = __expf(a.y - m);
    a.z = __expf(a.z - m); a.w = __expf(a.w - m);
    b.x = __expf(b.x - m); b.y = __expf(b.y - m);
    b.z = __expf(b.z - m); b.w = __expf(b.w - m);

    float s = (a.x + a.y + a.z + a.w) + (b.x + b.y + b.z + b.w);
    s = warpSum(s);
    if (!lane) sh[wid] = s;
    __syncthreads();
    if (tid < 32) {
        float t = (tid < 8) ? sh[tid] : 0.f;
        t = warpSum(t);
        if (!tid) sh[0] = t;
    }
    __syncthreads();
    float inv = 1.f / sh[0];

    a.x *= inv; a.y *= inv; a.z *= inv; a.w *= inv;
    b.x *= inv; b.y *= inv; b.z *= inv; b.w *= inv;
    *(float4*)(p + tid * 4) = a;
    *(float4*)(p + 1024 + tid * 4) = b;
}

__global__ __launch_bounds__(256) void ln_kernel(
    const float* __restrict__ q, const float* __restrict__ fc,
    const float* __restrict__ gamma, const float* __restrict__ beta,
    float* __restrict__ out)
{
    const size_t base = (size_t)blockIdx.x * DMODEL;
    const int tid = threadIdx.x;
    const int lane = tid & 31, wid = tid >> 5;
    __shared__ float shs[8];
    __shared__ float shq[8];

    float4 xq = *(const float4*)(q + base + tid * 4);
    float4 xf = *(const float4*)(fc + base + tid * 4);
    float x0 = xq.x + xf.x, x1 = xq.y + xf.y, x2 = xq.z + xf.z, x3 = xq.w + xf.w;

    float s  = x0 + x1 + x2 + x3;
    float sq = x0 * x0 + x1 * x1 + x2 * x2 + x3 * x3;
    s = warpSum(s);
    sq = warpSum(sq);
    if (!lane) { shs[wid] = s; shq[wid] = sq; }
    __syncthreads();
    if (tid < 32) {
        float ts = (tid < 8) ? shs[tid] : 0.f;
        float tq = (tid < 8) ? shq[tid] : 0.f;
        ts = warpSum(ts);
        tq = warpSum(tq);
        if (!tid) { shs[0] = ts; shq[0] = tq; }
    }
    __syncthreads();

    const float inv_n = 1.f / DMODEL;
    float mu  = shs[0] * inv_n;
    float var = shq[0] * inv_n - mu * mu;
    float r = rsqrtf(var + 1e-6f);

    float4 gg = *(const float4*)(gamma + tid * 4);
    float4 be = *(const float4*)(beta + tid * 4);
    float4 y;
    y.x = (x0 - mu) * r * gg.x + be.x;
    y.y = (x1 - mu) * r * gg.y + be.y;
    y.z = (x2 - mu) * r * gg.z + be.z;
    y.w = (x3 - mu) * r * gg.w + be.w;
    *(float4*)(out + base + tid * 4) = y;
}

// ===================== launch ===============================================
extern "C" void kernel_launch(void* const* d_in, const int* in_sizes, int n_in,
                              void* d_out, int out_size)
{
    const float* q     = (const float*)d_in[0];
    const float* k     = (const float*)d_in[1];
    const float* v     = (const float*)d_in[2];
    const float* Wq    = (const float*)d_in[3];
    const float* bq    = (const float*)d_in[4];
    const float* Wfc   = (const float*)d_in[5];
    const float* bfc   = (const float*)d_in[6];
    const float* gamma = (const float*)d_in[7];
    const float* beta  = (const float*)d_in[8];

    float* out      = (float*)d_out;
    float* x_out    = out;
    float* attn_out = out + PROJ_ELEMS;

    float* base = nullptr;
    cudaGetSymbolAddress((void**)&base, g_scratch);
    float* qh   = base;
    float* kh   = base + PROJ_ELEMS;
    float* vhT  = base + 2 * PROJ_ELEMS;   // [B,H,DK,S]
    float* ctx  = base + 3 * PROJ_ELEMS;
    float* fcb  = base + 4 * PROJ_ELEMS;
    float* WqT  = base + 5 * PROJ_ELEMS;
    float* WfcT = WqT + 1024 * 1024;

    dim3 blk(256);

    transpose_kernel<<<dim3(32, 32), dim3(32, 8)>>>(Wq, WqT);
    transpose_kernel<<<dim3(32, 32), dim3(32, 8)>>>(Wfc, WfcT);

    // Projections: X[8192,1024] x WqT[1024,K=1024] -> qh/kh [B,H,S,DK], vhT [B,H,DK,S]
    dim3 gproj(DMODEL / 128, NTOK / 128, 1);
    tc_gemm<128, EPI_PROJ ><<<gproj, blk>>>(q, WqT, bq, qh,  DMODEL, DMODEL, DMODEL);
    tc_gemm<128, EPI_PROJ ><<<gproj, blk>>>(k, WqT, bq, kh,  DMODEL, DMODEL, DMODEL);
    tc_gemm<128, EPI_PROJV><<<gproj, blk>>>(v, WqT, bq, vhT, DMODEL, DMODEL, DMODEL);

    // Scores: per (b,h): qh[2048,64] x kh[2048,64]^T -> attn (scaled)
    dim3 gsc(SEQ / 128, SEQ / 128, NBH);
    tc_gemm<128, EPI_SCORES><<<gsc, blk>>>(qh, kh, nullptr, attn_out,
                                           HDIM, HDIM, HDIM);

    softmax_kernel<<<NBH * SEQ, blk>>>(attn_out);

    // ctx: per (b,h): attn[2048,K=2048] x vhT[64,K=2048] -> ctx [B,S,H*DK]
    dim3 gctx(1, SEQ / 128, NBH);
    tc_gemm<64, EPI_CTX><<<gctx, blk>>>(attn_out, vhT, nullptr, ctx,
                                        SEQ, SEQ, SEQ);

    // Out projection: ctx[8192,1024] x WfcT[1024,K=1024] -> fcb
    dim3 gfc(DMODEL / 128, NTOK / 128, 1);
    tc_gemm<128, EPI_PLAIN><<<gfc, blk>>>(ctx, WfcT, bfc, fcb,
                                          DMODEL, DMODEL, DMODEL);

    ln_kernel<<<NTOK, blk>>>(q, fcb, gamma, beta, x_out);
}